// round 1
// baseline (speedup 1.0000x reference)
#include <cuda_runtime.h>
#include <math.h>

// ---------------- problem constants (fixed by the dataset) ----------------
#define NNODES   100000
#define NEDGES   600000
#define NEDGES2  1500000
#define HID      128
#define HF4      32          // HID/4
#define NLAYERS  3
#define NB       64

// ---------------- scratch (static device globals; no allocations) ----------
__device__ float g_h   [(size_t)NNODES * HID];   // node features (ping)
__device__ float g_aggN[(size_t)NNODES * HID];   // node aggregation buffer
__device__ float g_e   [(size_t)NEDGES * HID];   // edge features (ping)
__device__ float g_aggE[(size_t)NEDGES * HID];   // edge aggregation buffer
__device__ float g_rsNo[NNODES];                 // deg_out^-1/2 (node graph)
__device__ float g_rsNi[NNODES];                 // deg_in^-1/2
__device__ float g_rsEo[NEDGES];                 // deg_out^-1/2 (line graph)
__device__ float g_rsEi[NEDGES];                 // deg_in^-1/2
__device__ float g_pool[NB * 2 * HID];           // [B][2H] segment sums
__device__ float g_cnt [2 * NB];                 // [node counts | edge counts]

// ---------------- helpers ----------------
__device__ __forceinline__ void red_add_v4(float4* addr, float4 v) {
    asm volatile("red.global.add.v4.f32 [%0], {%1,%2,%3,%4};"
                 :: "l"(addr), "f"(v.x), "f"(v.y), "f"(v.z), "f"(v.w)
                 : "memory");
}

// ---------------- kernels ----------------
__global__ void k_zero(float* p, long n4) {
    long i = (long)blockIdx.x * blockDim.x + threadIdx.x;
    if (i < n4) ((float4*)p)[i] = make_float4(0.f, 0.f, 0.f, 0.f);
}

__global__ void k_deg(const int* __restrict__ s, const int* __restrict__ t,
                      float* dout, float* din, int n) {
    int i = blockIdx.x * blockDim.x + threadIdx.x;
    if (i < n) {
        atomicAdd(dout + s[i], 1.f);
        atomicAdd(din  + t[i], 1.f);
    }
}

__global__ void k_rsqrt2(float* a, float* b, int n) {
    int i = blockIdx.x * blockDim.x + threadIdx.x;
    if (i < n) {
        a[i] = rsqrtf(fmaxf(a[i], 1.f));
        b[i] = rsqrtf(fmaxf(b[i], 1.f));
    }
}

__global__ void k_hinit(const int* __restrict__ z, const float* __restrict__ emb,
                        float* __restrict__ h, int n) {
    long gid = (long)blockIdx.x * blockDim.x + threadIdx.x;
    int i = (int)(gid >> 5), c = (int)(gid & 31);
    if (i < n)
        ((float4*)h)[(long)i * HF4 + c] = ((const float4*)emb)[(long)z[i] * HF4 + c];
}

__global__ void k_einit(const float* __restrict__ d, const float* __restrict__ w,
                        const float* __restrict__ b, float* __restrict__ e, int n) {
    long gid = (long)blockIdx.x * blockDim.x + threadIdx.x;
    int i = (int)(gid >> 5), c = (int)(gid & 31);
    if (i >= n) return;
    float dv = __ldg(d + i);
    float4 wv = ((const float4*)w)[c];
    float4 bv = ((const float4*)b)[c];
    float4 o = make_float4(dv * wv.x + bv.x, dv * wv.y + bv.y,
                           dv * wv.z + bv.z, dv * wv.w + bv.w);
    ((float4*)e)[(long)i * HF4 + c] = o;
}

// agg[dst] += feat[src] * rs_out[src]   (one warp per edge, float4 per lane)
__global__ void k_scatter(const float* __restrict__ feat, const float* __restrict__ rs,
                          const int* __restrict__ s, const int* __restrict__ t,
                          float* __restrict__ agg, int ne) {
    long gid = (long)blockIdx.x * blockDim.x + threadIdx.x;
    int e = (int)(gid >> 5), c = (int)(gid & 31);
    if (e >= ne) return;
    int si = s[e], ti = t[e];
    float4 v = ((const float4*)feat)[(long)si * HF4 + c];
    float sc = __ldg(rs + si);
    v.x *= sc; v.y *= sc; v.z *= sc; v.w *= sc;
    red_add_v4(((float4*)agg) + (long)ti * HF4 + c, v);
}

// out = relu( (X * rs[:,None]) @ W + b )  for X:[rows,128], W:[128,128]
// 256 threads / 64 rows per block; W + X tile in smem; 8x4 register tile.
__global__ void __launch_bounds__(256, 2)
k_gemm_relu(const float* __restrict__ X, const float* __restrict__ rs,
            const float* __restrict__ W, const float* __restrict__ bias,
            float* __restrict__ out, int rows) {
    extern __shared__ float smem[];
    float* Ws = smem;                 // 128*128
    float* Xs = smem + 128 * 128;     // 64*128
    int tid = threadIdx.x;
    long r0 = (long)blockIdx.x * 64;

    float4* Ws4 = (float4*)Ws;
    const float4* W4 = (const float4*)W;
#pragma unroll
    for (int i = tid; i < 4096; i += 256) Ws4[i] = W4[i];

    float4* Xs4 = (float4*)Xs;
    const float4* X4 = (const float4*)X;
    for (int i = tid; i < 2048; i += 256) {
        int rl = i >> 5;
        long r = r0 + rl;
        float4 v = make_float4(0.f, 0.f, 0.f, 0.f);
        if (r < rows) {
            v = X4[r * HF4 + (i & 31)];
            float sc = rs[r];
            v.x *= sc; v.y *= sc; v.z *= sc; v.w *= sc;
        }
        Xs4[i] = v;
    }
    __syncthreads();

    int c = tid & 31;          // column group: cols 4c..4c+3
    int rg = tid >> 5;         // row group: rows rg*8..rg*8+7
    float4 acc[8];
#pragma unroll
    for (int i = 0; i < 8; i++) acc[i] = make_float4(0.f, 0.f, 0.f, 0.f);

    const float* xbase = Xs + rg * 8 * 128;
#pragma unroll 4
    for (int k = 0; k < 128; k++) {
        float4 w = Ws4[k * 32 + c];
#pragma unroll
        for (int i = 0; i < 8; i++) {
            float x = xbase[i * 128 + k];
            acc[i].x += x * w.x;
            acc[i].y += x * w.y;
            acc[i].z += x * w.z;
            acc[i].w += x * w.w;
        }
    }

    float4 bb = ((const float4*)bias)[c];
#pragma unroll
    for (int i = 0; i < 8; i++) {
        long r = r0 + rg * 8 + i;
        if (r < rows) {
            float4 o;
            o.x = fmaxf(acc[i].x + bb.x, 0.f);
            o.y = fmaxf(acc[i].y + bb.y, 0.f);
            o.z = fmaxf(acc[i].z + bb.z, 0.f);
            o.w = fmaxf(acc[i].w + bb.w, 0.f);
            ((float4*)out)[r * HF4 + c] = o;
        }
    }
}

// segment sum into pool[g][coloff..] + counts
__global__ void k_pool(const float* __restrict__ feat, const int* __restrict__ seg,
                       float* __restrict__ pool, float* __restrict__ cnt,
                       int coloff4, int cntoff, int n) {
    long gid = (long)blockIdx.x * blockDim.x + threadIdx.x;
    int i = (int)(gid >> 5), c = (int)(gid & 31);
    if (i >= n) return;
    int g = seg[i];
    float4 v = ((const float4*)feat)[(long)i * HF4 + c];
    red_add_v4(((float4*)pool) + (long)g * 64 + coloff4 + c, v);
    if (c == 0) atomicAdd(cnt + cntoff + g, 1.f);
}

// final MLP: one block per graph (128 threads)
__global__ void k_readout(const float* __restrict__ pool, const float* __restrict__ cnt,
                          const float* __restrict__ r1w, const float* __restrict__ r1b,
                          const float* __restrict__ r2w, const float* __restrict__ r2b,
                          float* __restrict__ out) {
    __shared__ float x[256];
    __shared__ float redbuf[128];
    int g = blockIdx.x, tid = threadIdx.x;
    float cn = fmaxf(cnt[g], 1.f);
    float ce = fmaxf(cnt[NB + g], 1.f);
    x[tid]       = pool[g * 256 + tid] / cn;
    x[128 + tid] = pool[g * 256 + 128 + tid] / ce;
    __syncthreads();
    float a = r1b[tid];
#pragma unroll 8
    for (int k = 0; k < 256; k++) a += x[k] * r1w[k * 128 + tid];
    float sig = 1.f / (1.f + expf(-a));
    float p = a * sig * r2w[tid];
    redbuf[tid] = p;
    __syncthreads();
    for (int s = 64; s > 0; s >>= 1) {
        if (tid < s) redbuf[tid] += redbuf[tid + s];
        __syncthreads();
    }
    if (tid == 0) out[g] = redbuf[0] + r2b[0];
}

// ---------------- launch ----------------
static inline int cdiv(long a, long b) { return (int)((a + b - 1) / b); }

extern "C" void kernel_launch(void* const* d_in, const int* in_sizes, int n_in,
                              void* d_out, int out_size) {
    const int*   z    = (const int*)  d_in[0];
    const float* d    = (const float*)d_in[1];
    const int*   src  = (const int*)  d_in[2];
    const int*   dst  = (const int*)  d_in[3];
    const int*   lsrc = (const int*)  d_in[4];
    const int*   ldst = (const int*)  d_in[5];
    const int*   ng   = (const int*)  d_in[6];
    const int*   eg   = (const int*)  d_in[7];
    const float* emb  = (const float*)d_in[8];
    const float* epw  = (const float*)d_in[9];
    const float* epb  = (const float*)d_in[10];
    const float* gW   = (const float*)d_in[11];
    const float* gb   = (const float*)d_in[12];
    const float* lgW  = (const float*)d_in[13];
    const float* lgb  = (const float*)d_in[14];
    const float* r1w  = (const float*)d_in[15];
    const float* r1b  = (const float*)d_in[16];
    const float* r2w  = (const float*)d_in[17];
    const float* r2b  = (const float*)d_in[18];
    float* out = (float*)d_out;

    float *p_h, *p_aggN, *p_e, *p_aggE, *p_rsNo, *p_rsNi, *p_rsEo, *p_rsEi, *p_pool, *p_cnt;
    cudaGetSymbolAddress((void**)&p_h,    g_h);
    cudaGetSymbolAddress((void**)&p_aggN, g_aggN);
    cudaGetSymbolAddress((void**)&p_e,    g_e);
    cudaGetSymbolAddress((void**)&p_aggE, g_aggE);
    cudaGetSymbolAddress((void**)&p_rsNo, g_rsNo);
    cudaGetSymbolAddress((void**)&p_rsNi, g_rsNi);
    cudaGetSymbolAddress((void**)&p_rsEo, g_rsEo);
    cudaGetSymbolAddress((void**)&p_rsEi, g_rsEi);
    cudaGetSymbolAddress((void**)&p_pool, g_pool);
    cudaGetSymbolAddress((void**)&p_cnt,  g_cnt);

    cudaFuncSetAttribute(k_gemm_relu, cudaFuncAttributeMaxDynamicSharedMemorySize, 98304);

    const int T = 256;

    // degrees (computed once; shared by all 3 layers of each graph)
    k_zero<<<cdiv(NNODES / 4, T), T>>>(p_rsNo, NNODES / 4);
    k_zero<<<cdiv(NNODES / 4, T), T>>>(p_rsNi, NNODES / 4);
    k_zero<<<cdiv(NEDGES / 4, T), T>>>(p_rsEo, NEDGES / 4);
    k_zero<<<cdiv(NEDGES / 4, T), T>>>(p_rsEi, NEDGES / 4);
    k_deg<<<cdiv(NEDGES, T), T>>>(src, dst, p_rsNo, p_rsNi, NEDGES);
    k_deg<<<cdiv(NEDGES2, T), T>>>(lsrc, ldst, p_rsEo, p_rsEi, NEDGES2);
    k_rsqrt2<<<cdiv(NNODES, T), T>>>(p_rsNo, p_rsNi, NNODES);
    k_rsqrt2<<<cdiv(NEDGES, T), T>>>(p_rsEo, p_rsEi, NEDGES);

    // embeddings
    k_hinit<<<cdiv((long)NNODES * 32, T), T>>>(z, emb, p_h, NNODES);
    k_einit<<<cdiv((long)NEDGES * 32, T), T>>>(d, epw, epb, p_e, NEDGES);

    // node-graph conv layers
    for (int l = 0; l < NLAYERS; l++) {
        k_zero<<<cdiv((long)NNODES * 32, T), T>>>(p_aggN, (long)NNODES * 32);
        k_scatter<<<cdiv((long)NEDGES * 32, T), T>>>(p_h, p_rsNo, src, dst, p_aggN, NEDGES);
        k_gemm_relu<<<cdiv(NNODES, 64), T, 98304>>>(p_aggN, p_rsNi,
                                                    gW + (long)l * HID * HID,
                                                    gb + (long)l * HID, p_h, NNODES);
    }
    // line-graph conv layers
    for (int l = 0; l < NLAYERS; l++) {
        k_zero<<<cdiv((long)NEDGES * 32, T), T>>>(p_aggE, (long)NEDGES * 32);
        k_scatter<<<cdiv((long)NEDGES2 * 32, T), T>>>(p_e, p_rsEo, lsrc, ldst, p_aggE, NEDGES2);
        k_gemm_relu<<<cdiv(NEDGES, 64), T, 98304>>>(p_aggE, p_rsEi,
                                                    lgW + (long)l * HID * HID,
                                                    lgb + (long)l * HID, p_e, NEDGES);
    }

    // pooling + readout
    k_zero<<<cdiv(NB * 2 * HID / 4, T), T>>>(p_pool, NB * 2 * HID / 4);
    k_zero<<<1, 32>>>(p_cnt, 2 * NB / 4);
    k_pool<<<cdiv((long)NNODES * 32, T), T>>>(p_h, ng, p_pool, p_cnt, 0, 0, NNODES);
    k_pool<<<cdiv((long)NEDGES * 32, T), T>>>(p_e, eg, p_pool, p_cnt, 32, NB, NEDGES);
    k_readout<<<NB, 128>>>(p_pool, p_cnt, r1w, r1b, r2w, r2b, out);
}

// round 2
// speedup vs baseline: 1.0669x; 1.0669x over previous
#include <cuda_runtime.h>
#include <math.h>
#include <stdint.h>

// ---------------- problem constants (fixed by the dataset) ----------------
#define NNODES   100000
#define NEDGES   600000
#define NEDGES2  1500000
#define HID      128
#define HF4      32          // HID/4
#define NLAYERS  3
#define NB       64

// ---------------- scratch (static device globals; no allocations) ----------
__device__ float g_h   [(size_t)NNODES * HID];
__device__ float g_aggN[(size_t)NNODES * HID];
__device__ float g_e   [(size_t)NEDGES * HID];
__device__ float g_aggE[(size_t)NEDGES * HID];
__device__ float g_rsNo[NNODES];
__device__ float g_rsNi[NNODES];
__device__ float g_rsEo[NEDGES];
__device__ float g_rsEi[NEDGES];
__device__ float g_pool[NB * 2 * HID];
__device__ float g_cnt [2 * NB];

// ---------------- helpers ----------------
__device__ __forceinline__ void red_add_v4(float4* addr, float4 v) {
    asm volatile("red.global.add.v4.f32 [%0], {%1,%2,%3,%4};"
                 :: "l"(addr), "f"(v.x), "f"(v.y), "f"(v.z), "f"(v.w)
                 : "memory");
}

__device__ __forceinline__ uint32_t f2tf32(float f) {
    uint32_t r;
    asm("cvt.rna.tf32.f32 %0, %1;" : "=r"(r) : "f"(f));
    return r;
}

__device__ __forceinline__ void mma_tf32(float& c0, float& c1, float& c2, float& c3,
                                         uint32_t a0, uint32_t a1, uint32_t a2, uint32_t a3,
                                         uint32_t b0, uint32_t b1) {
    asm volatile("mma.sync.aligned.m16n8k8.row.col.f32.tf32.tf32.f32 "
                 "{%0,%1,%2,%3}, {%4,%5,%6,%7}, {%8,%9}, {%0,%1,%2,%3};"
                 : "+f"(c0), "+f"(c1), "+f"(c2), "+f"(c3)
                 : "r"(a0), "r"(a1), "r"(a2), "r"(a3), "r"(b0), "r"(b1));
}

// ---------------- kernels ----------------
__global__ void k_zero(float* p, long n4) {
    long i = (long)blockIdx.x * blockDim.x + threadIdx.x;
    if (i < n4) ((float4*)p)[i] = make_float4(0.f, 0.f, 0.f, 0.f);
}

__global__ void k_deg(const int* __restrict__ s, const int* __restrict__ t,
                      float* dout, float* din, int n) {
    int i = blockIdx.x * blockDim.x + threadIdx.x;
    if (i < n) {
        atomicAdd(dout + s[i], 1.f);
        atomicAdd(din  + t[i], 1.f);
    }
}

__global__ void k_rsqrt2(float* a, float* b, int n) {
    int i = blockIdx.x * blockDim.x + threadIdx.x;
    if (i < n) {
        a[i] = rsqrtf(fmaxf(a[i], 1.f));
        b[i] = rsqrtf(fmaxf(b[i], 1.f));
    }
}

__global__ void k_hinit(const int* __restrict__ z, const float* __restrict__ emb,
                        float* __restrict__ h, int n) {
    long gid = (long)blockIdx.x * blockDim.x + threadIdx.x;
    int i = (int)(gid >> 5), c = (int)(gid & 31);
    if (i < n)
        ((float4*)h)[(long)i * HF4 + c] = ((const float4*)emb)[(long)z[i] * HF4 + c];
}

__global__ void k_einit(const float* __restrict__ d, const float* __restrict__ w,
                        const float* __restrict__ b, float* __restrict__ e, int n) {
    long gid = (long)blockIdx.x * blockDim.x + threadIdx.x;
    int i = (int)(gid >> 5), c = (int)(gid & 31);
    if (i >= n) return;
    float dv = __ldg(d + i);
    float4 wv = ((const float4*)w)[c];
    float4 bv = ((const float4*)b)[c];
    float4 o = make_float4(dv * wv.x + bv.x, dv * wv.y + bv.y,
                           dv * wv.z + bv.z, dv * wv.w + bv.w);
    ((float4*)e)[(long)i * HF4 + c] = o;
}

// agg[dst] += feat[src] * rs_out[src]   (one warp per edge, float4 per lane)
__global__ void k_scatter(const float* __restrict__ feat, const float* __restrict__ rs,
                          const int* __restrict__ s, const int* __restrict__ t,
                          float* __restrict__ agg, int ne) {
    long gid = (long)blockIdx.x * blockDim.x + threadIdx.x;
    int e = (int)(gid >> 5), c = (int)(gid & 31);
    if (e >= ne) return;
    int si = s[e], ti = t[e];
    float4 v = ((const float4*)feat)[(long)si * HF4 + c];
    float sc = __ldg(rs + si);
    v.x *= sc; v.y *= sc; v.z *= sc; v.w *= sc;
    red_add_v4(((float4*)agg) + (long)ti * HF4 + c, v);
}

// ---------------- tensor-core GEMM: out = relu((X * rs[:,None]) @ W + b) ----
// X:[rows,128] fp32, W:[128,128] fp32 (k-major). Block = 128 thr = 4 warps,
// tile 64 rows x 128 cols. tf32 mma.sync m16n8k8. Smem: X tile (64x132 pad),
// W^T tile (128x132 pad) -> conflict-free fragment loads.
#define XS_STRIDE 132
__global__ void __launch_bounds__(128, 2)
k_gemm_tc(const float* __restrict__ X, const float* __restrict__ rs,
          const float* __restrict__ W, const float* __restrict__ bias,
          float* __restrict__ out, int rows) {
    extern __shared__ __align__(16) float smem[];
    uint32_t* Xs = (uint32_t*)smem;                        // 64 x 132
    uint32_t* Ws = (uint32_t*)(smem + 64 * XS_STRIDE);     // 128 x 132 (n-major, transposed)
    int tid = threadIdx.x;
    int warp = tid >> 5, lane = tid & 31;
    int g = lane >> 2, tig = lane & 3;
    long r0 = (long)blockIdx.x * 64;

    // stage X tile: scale by rs, convert to tf32
    {
        const float4* X4 = (const float4*)X;
        for (int i = tid; i < 64 * 32; i += 128) {
            int rl = i >> 5, c = i & 31;
            long r = r0 + rl;
            float4 v = make_float4(0.f, 0.f, 0.f, 0.f);
            if (r < rows) {
                v = X4[r * HF4 + c];
                float sc = __ldg(rs + r);
                v.x *= sc; v.y *= sc; v.z *= sc; v.w *= sc;
            }
            uint32_t* p = Xs + rl * XS_STRIDE + c * 4;
            p[0] = f2tf32(v.x); p[1] = f2tf32(v.y);
            p[2] = f2tf32(v.z); p[3] = f2tf32(v.w);
        }
    }
    // stage W transposed: Ws[n][k] = W[k][n]
    for (int i = tid; i < 128 * 128; i += 128) {
        int k = i >> 7, n = i & 127;
        Ws[n * XS_STRIDE + k] = f2tf32(__ldg(W + i));
    }
    __syncthreads();

    float acc[16][4];
#pragma unroll
    for (int nf = 0; nf < 16; nf++)
#pragma unroll
        for (int j = 0; j < 4; j++) acc[nf][j] = 0.f;

    const uint32_t* xa = Xs + (warp * 16 + g) * XS_STRIDE + tig;
#pragma unroll 4
    for (int ks = 0; ks < 16; ks++) {
        int k0 = ks * 8;
        uint32_t a0 = xa[k0];
        uint32_t a1 = xa[8 * XS_STRIDE + k0];
        uint32_t a2 = xa[k0 + 4];
        uint32_t a3 = xa[8 * XS_STRIDE + k0 + 4];
#pragma unroll
        for (int nf = 0; nf < 16; nf++) {
            const uint32_t* wb = Ws + (nf * 8 + g) * XS_STRIDE + k0 + tig;
            uint32_t b0 = wb[0];
            uint32_t b1 = wb[4];
            mma_tf32(acc[nf][0], acc[nf][1], acc[nf][2], acc[nf][3],
                     a0, a1, a2, a3, b0, b1);
        }
    }

    // epilogue: +bias, relu, store
    long row0 = r0 + warp * 16 + g;
    long row1 = row0 + 8;
#pragma unroll
    for (int nf = 0; nf < 16; nf++) {
        int n0 = nf * 8 + 2 * tig;
        float b0 = __ldg(bias + n0), b1 = __ldg(bias + n0 + 1);
        if (row0 < rows) {
            float2 o;
            o.x = fmaxf(acc[nf][0] + b0, 0.f);
            o.y = fmaxf(acc[nf][1] + b1, 0.f);
            *(float2*)(out + row0 * HID + n0) = o;
        }
        if (row1 < rows) {
            float2 o;
            o.x = fmaxf(acc[nf][2] + b0, 0.f);
            o.y = fmaxf(acc[nf][3] + b1, 0.f);
            *(float2*)(out + row1 * HID + n0) = o;
        }
    }
}

// segment sum into pool[g][coloff..] + counts
__global__ void k_pool(const float* __restrict__ feat, const int* __restrict__ seg,
                       float* __restrict__ pool, float* __restrict__ cnt,
                       int coloff4, int cntoff, int n) {
    long gid = (long)blockIdx.x * blockDim.x + threadIdx.x;
    int i = (int)(gid >> 5), c = (int)(gid & 31);
    if (i >= n) return;
    int g = seg[i];
    float4 v = ((const float4*)feat)[(long)i * HF4 + c];
    red_add_v4(((float4*)pool) + (long)g * 64 + coloff4 + c, v);
    if (c == 0) atomicAdd(cnt + cntoff + g, 1.f);
}

// final MLP: one block per graph (128 threads)
__global__ void k_readout(const float* __restrict__ pool, const float* __restrict__ cnt,
                          const float* __restrict__ r1w, const float* __restrict__ r1b,
                          const float* __restrict__ r2w, const float* __restrict__ r2b,
                          float* __restrict__ out) {
    __shared__ float x[256];
    __shared__ float redbuf[128];
    int g = blockIdx.x, tid = threadIdx.x;
    float cn = fmaxf(cnt[g], 1.f);
    float ce = fmaxf(cnt[NB + g], 1.f);
    x[tid]       = pool[g * 256 + tid] / cn;
    x[128 + tid] = pool[g * 256 + 128 + tid] / ce;
    __syncthreads();
    float a = r1b[tid];
#pragma unroll 8
    for (int k = 0; k < 256; k++) a += x[k] * r1w[k * 128 + tid];
    float sig = 1.f / (1.f + expf(-a));
    float p = a * sig * r2w[tid];
    redbuf[tid] = p;
    __syncthreads();
    for (int s = 64; s > 0; s >>= 1) {
        if (tid < s) redbuf[tid] += redbuf[tid + s];
        __syncthreads();
    }
    if (tid == 0) out[g] = redbuf[0] + r2b[0];
}

// ---------------- launch ----------------
static inline int cdiv(long a, long b) { return (int)((a + b - 1) / b); }

extern "C" void kernel_launch(void* const* d_in, const int* in_sizes, int n_in,
                              void* d_out, int out_size) {
    const int*   z    = (const int*)  d_in[0];
    const float* d    = (const float*)d_in[1];
    const int*   src  = (const int*)  d_in[2];
    const int*   dst  = (const int*)  d_in[3];
    const int*   lsrc = (const int*)  d_in[4];
    const int*   ldst = (const int*)  d_in[5];
    const int*   ng   = (const int*)  d_in[6];
    const int*   eg   = (const int*)  d_in[7];
    const float* emb  = (const float*)d_in[8];
    const float* epw  = (const float*)d_in[9];
    const float* epb  = (const float*)d_in[10];
    const float* gW   = (const float*)d_in[11];
    const float* gb   = (const float*)d_in[12];
    const float* lgW  = (const float*)d_in[13];
    const float* lgb  = (const float*)d_in[14];
    const float* r1w  = (const float*)d_in[15];
    const float* r1b  = (const float*)d_in[16];
    const float* r2w  = (const float*)d_in[17];
    const float* r2b  = (const float*)d_in[18];
    float* out = (float*)d_out;

    float *p_h, *p_aggN, *p_e, *p_aggE, *p_rsNo, *p_rsNi, *p_rsEo, *p_rsEi, *p_pool, *p_cnt;
    cudaGetSymbolAddress((void**)&p_h,    g_h);
    cudaGetSymbolAddress((void**)&p_aggN, g_aggN);
    cudaGetSymbolAddress((void**)&p_e,    g_e);
    cudaGetSymbolAddress((void**)&p_aggE, g_aggE);
    cudaGetSymbolAddress((void**)&p_rsNo, g_rsNo);
    cudaGetSymbolAddress((void**)&p_rsNi, g_rsNi);
    cudaGetSymbolAddress((void**)&p_rsEo, g_rsEo);
    cudaGetSymbolAddress((void**)&p_rsEi, g_rsEi);
    cudaGetSymbolAddress((void**)&p_pool, g_pool);
    cudaGetSymbolAddress((void**)&p_cnt,  g_cnt);

    const int smem_gemm = (64 * XS_STRIDE + 128 * XS_STRIDE) * 4;  // ~101 KB
    cudaFuncSetAttribute(k_gemm_tc, cudaFuncAttributeMaxDynamicSharedMemorySize, smem_gemm);

    const int T = 256;

    // degrees (computed once; shared by all 3 layers of each graph)
    k_zero<<<cdiv(NNODES / 4, T), T>>>(p_rsNo, NNODES / 4);
    k_zero<<<cdiv(NNODES / 4, T), T>>>(p_rsNi, NNODES / 4);
    k_zero<<<cdiv(NEDGES / 4, T), T>>>(p_rsEo, NEDGES / 4);
    k_zero<<<cdiv(NEDGES / 4, T), T>>>(p_rsEi, NEDGES / 4);
    k_deg<<<cdiv(NEDGES, T), T>>>(src, dst, p_rsNo, p_rsNi, NEDGES);
    k_deg<<<cdiv(NEDGES2, T), T>>>(lsrc, ldst, p_rsEo, p_rsEi, NEDGES2);
    k_rsqrt2<<<cdiv(NNODES, T), T>>>(p_rsNo, p_rsNi, NNODES);
    k_rsqrt2<<<cdiv(NEDGES, T), T>>>(p_rsEo, p_rsEi, NEDGES);

    // embeddings
    k_hinit<<<cdiv((long)NNODES * 32, T), T>>>(z, emb, p_h, NNODES);
    k_einit<<<cdiv((long)NEDGES * 32, T), T>>>(d, epw, epb, p_e, NEDGES);

    // node-graph conv layers
    for (int l = 0; l < NLAYERS; l++) {
        k_zero<<<cdiv((long)NNODES * 32, T), T>>>(p_aggN, (long)NNODES * 32);
        k_scatter<<<cdiv((long)NEDGES * 32, T), T>>>(p_h, p_rsNo, src, dst, p_aggN, NEDGES);
        k_gemm_tc<<<cdiv(NNODES, 64), 128, smem_gemm>>>(p_aggN, p_rsNi,
                                                        gW + (long)l * HID * HID,
                                                        gb + (long)l * HID, p_h, NNODES);
    }
    // line-graph conv layers
    for (int l = 0; l < NLAYERS; l++) {
        k_zero<<<cdiv((long)NEDGES * 32, T), T>>>(p_aggE, (long)NEDGES * 32);
        k_scatter<<<cdiv((long)NEDGES2 * 32, T), T>>>(p_e, p_rsEo, lsrc, ldst, p_aggE, NEDGES2);
        k_gemm_tc<<<cdiv(NEDGES, 64), 128, smem_gemm>>>(p_aggE, p_rsEi,
                                                        lgW + (long)l * HID * HID,
                                                        lgb + (long)l * HID, p_e, NEDGES);
    }

    // pooling + readout
    k_zero<<<cdiv(NB * 2 * HID / 4, T), T>>>(p_pool, NB * 2 * HID / 4);
    k_zero<<<1, 32>>>(p_cnt, 2 * NB / 4);
    k_pool<<<cdiv((long)NNODES * 32, T), T>>>(p_h, ng, p_pool, p_cnt, 0, 0, NNODES);
    k_pool<<<cdiv((long)NEDGES * 32, T), T>>>(p_e, eg, p_pool, p_cnt, 32, NB, NEDGES);
    k_readout<<<NB, 128>>>(p_pool, p_cnt, r1w, r1b, r2w, r2b, out);
}

// round 4
// speedup vs baseline: 1.3050x; 1.2232x over previous
#include <cuda_runtime.h>
#include <math.h>
#include <stdint.h>

// ---------------- problem constants ----------------
#define NNODES   100000
#define NEDGES   600000
#define NEDGES2  1500000
#define HID      128
#define HF4      32
#define NLAYERS  3
#define NB       64
#define WT_LAYER 8192   // float2 entries per layer in g_Wt (16 ks * 16 nf * 32 lanes)

// ---------------- scratch ----------------
__device__ float g_h   [(size_t)NNODES * HID];
__device__ float g_aggN[(size_t)NNODES * HID];
__device__ float g_e   [(size_t)NEDGES * HID];
__device__ float g_aggE[(size_t)NEDGES * HID];
__device__ float g_degN[2 * NNODES];             // [out | in]
__device__ float g_degE[2 * NEDGES];             // [out | in]
__device__ float g_Wt  [6 * WT_LAYER * 2];       // per-layer fragment-ordered tf32 W
__device__ float g_pool[NB * 2 * HID];
__device__ float g_cnt [2 * NB];

// ---------------- helpers ----------------
__device__ __forceinline__ void red_add_v4(float4* addr, float4 v) {
    asm volatile("red.global.add.v4.f32 [%0], {%1,%2,%3,%4};"
                 :: "l"(addr), "f"(v.x), "f"(v.y), "f"(v.z), "f"(v.w)
                 : "memory");
}
__device__ __forceinline__ uint32_t f2tf32(float f) {
    uint32_t r;
    asm("cvt.rna.tf32.f32 %0, %1;" : "=r"(r) : "f"(f));
    return r;
}
__device__ __forceinline__ void mma_tf32(float& c0, float& c1, float& c2, float& c3,
                                         uint32_t a0, uint32_t a1, uint32_t a2, uint32_t a3,
                                         uint32_t b0, uint32_t b1) {
    asm volatile("mma.sync.aligned.m16n8k8.row.col.f32.tf32.tf32.f32 "
                 "{%0,%1,%2,%3}, {%4,%5,%6,%7}, {%8,%9}, {%0,%1,%2,%3};"
                 : "+f"(c0), "+f"(c1), "+f"(c2), "+f"(c3)
                 : "r"(a0), "r"(a1), "r"(a2), "r"(a3), "r"(b0), "r"(b1));
}
__device__ __forceinline__ float rsdeg(const float* deg, long i) {
    return rsqrtf(fmaxf(__ldg(deg + i), 1.f));
}

// ---------------- kernels ----------------
__global__ void k_zero(float* p, long n4) {
    long i = (long)blockIdx.x * blockDim.x + threadIdx.x;
    if (i < n4) ((float4*)p)[i] = make_float4(0.f, 0.f, 0.f, 0.f);
}

// Precompute fragment-ordered tf32 weights for all 6 layers.
// Wt[layer][ks][nf][lane] = { tf32(W[k][n]), tf32(W[k+4][n]) },
//   lane: g=lane>>2, tig=lane&3; n = nf*8+g; k = ks*8+tig.
__global__ void k_wt(const float* __restrict__ gW, const float* __restrict__ lgW,
                     float* __restrict__ Wt) {
    int idx = blockIdx.x * blockDim.x + threadIdx.x;   // 0 .. 49151
    if (idx >= 6 * WT_LAYER) return;
    int layer = idx >> 13;
    int rem = idx & 8191;
    int ks = rem >> 9;
    int rem2 = rem & 511;
    int nf = rem2 >> 5, lane = rem2 & 31;
    int g = lane >> 2, tig = lane & 3;
    int n = nf * 8 + g, k = ks * 8 + tig;
    const float* W = (layer < 3) ? (gW + (long)layer * 16384)
                                 : (lgW + (long)(layer - 3) * 16384);
    uint32_t b0 = f2tf32(__ldg(W + k * HID + n));
    uint32_t b1 = f2tf32(__ldg(W + (k + 4) * HID + n));
    Wt[(long)idx * 2 + 0] = __uint_as_float(b0);
    Wt[(long)idx * 2 + 1] = __uint_as_float(b1);
}

__global__ void k_deg(const int* __restrict__ s, const int* __restrict__ t,
                      float* deg, int noff, int n) {
    int i = blockIdx.x * blockDim.x + threadIdx.x;
    if (i < n) {
        atomicAdd(deg + s[i], 1.f);
        atomicAdd(deg + noff + t[i], 1.f);
    }
}

// generic scatter: agg[dst] += feat[src] * deg_out[src]^-1/2  (warp/edge)
__global__ void k_scatter(const float* __restrict__ feat, const float* __restrict__ degO,
                          const int* __restrict__ s, const int* __restrict__ t,
                          float* __restrict__ agg, int ne) {
    long gid = (long)blockIdx.x * blockDim.x + threadIdx.x;
    int e = (int)(gid >> 5), c = (int)(gid & 31);
    if (e >= ne) return;
    int si = s[e], ti = t[e];
    float4 v = ((const float4*)feat)[(long)si * HF4 + c];
    float sc = rsdeg(degO, si);
    v.x *= sc; v.y *= sc; v.z *= sc; v.w *= sc;
    red_add_v4(((float4*)agg) + (long)ti * HF4 + c, v);
}

// first line-graph layer: edge feature computed on the fly from d
__global__ void k_scatter_e0(const float* __restrict__ d, const float* __restrict__ epw,
                             const float* __restrict__ epb, const float* __restrict__ degO,
                             const int* __restrict__ s, const int* __restrict__ t,
                             float* __restrict__ agg, int ne) {
    long gid = (long)blockIdx.x * blockDim.x + threadIdx.x;
    int e = (int)(gid >> 5), c = (int)(gid & 31);
    if (e >= ne) return;
    int si = s[e], ti = t[e];
    float dv = __ldg(d + si);
    float sc = rsdeg(degO, si);
    float4 w = ((const float4*)epw)[c];
    float4 b = ((const float4*)epb)[c];
    float4 v = make_float4((dv * w.x + b.x) * sc, (dv * w.y + b.y) * sc,
                           (dv * w.z + b.z) * sc, (dv * w.w + b.w) * sc);
    red_add_v4(((float4*)agg) + (long)ti * HF4 + c, v);
}

// first node-graph layer: feature = emb[z[src]]
__global__ void k_scatter_h0(const int* __restrict__ z, const float* __restrict__ emb,
                             const float* __restrict__ degO,
                             const int* __restrict__ s, const int* __restrict__ t,
                             float* __restrict__ agg, int ne) {
    long gid = (long)blockIdx.x * blockDim.x + threadIdx.x;
    int e = (int)(gid >> 5), c = (int)(gid & 31);
    if (e >= ne) return;
    int si = s[e], ti = t[e];
    int zi = __ldg(z + si);
    float4 v = ((const float4*)emb)[(long)zi * HF4 + c];
    float sc = rsdeg(degO, si);
    v.x *= sc; v.y *= sc; v.z *= sc; v.w *= sc;
    red_add_v4(((float4*)agg) + (long)ti * HF4 + c, v);
}

// ---------------- tensor-core GEMM: out = relu((X * rsdeg_in) @ W + b) ------
// Block 128 thr / 4 warps, tile 64x128. A from smem (64x132), B fragments via
// coalesced LDG.64 from pre-swizzled L1-resident g_Wt table.
#define XS_STRIDE 132
__global__ void __launch_bounds__(128)
k_gemm_tc(const float* __restrict__ X, const float* __restrict__ degI,
          const float2* __restrict__ Wt, const float* __restrict__ bias,
          float* __restrict__ out, int rows) {
    __shared__ __align__(16) uint32_t Xs[64 * XS_STRIDE];
    int tid = threadIdx.x;
    int warp = tid >> 5, lane = tid & 31;
    int g = lane >> 2, tig = lane & 3;
    long r0 = (long)blockIdx.x * 64;

    // stage X tile: scale by rsdeg_in, convert to tf32
    {
        const float4* X4 = (const float4*)X;
        for (int i = tid; i < 64 * 32; i += 128) {
            int rl = i >> 5, c = i & 31;
            long r = r0 + rl;
            float4 v = make_float4(0.f, 0.f, 0.f, 0.f);
            if (r < rows) {
                v = X4[r * HF4 + c];
                float sc = rsdeg(degI, r);
                v.x *= sc; v.y *= sc; v.z *= sc; v.w *= sc;
            }
            uint32_t* p = Xs + rl * XS_STRIDE + c * 4;
            p[0] = f2tf32(v.x); p[1] = f2tf32(v.y);
            p[2] = f2tf32(v.z); p[3] = f2tf32(v.w);
        }
    }
    __syncthreads();

    float acc[16][4];
#pragma unroll
    for (int nf = 0; nf < 16; nf++)
#pragma unroll
        for (int j = 0; j < 4; j++) acc[nf][j] = 0.f;

    const uint32_t* xa = Xs + (warp * 16 + g) * XS_STRIDE + tig;
    const uint2* wt = ((const uint2*)Wt) + lane;
#pragma unroll 4
    for (int ks = 0; ks < 16; ks++) {
        int k0 = ks * 8;
        uint32_t a0 = xa[k0];
        uint32_t a1 = xa[8 * XS_STRIDE + k0];
        uint32_t a2 = xa[k0 + 4];
        uint32_t a3 = xa[8 * XS_STRIDE + k0 + 4];
#pragma unroll
        for (int nf = 0; nf < 16; nf++) {
            uint2 b = __ldg(wt + (ks * 16 + nf) * 32);
            mma_tf32(acc[nf][0], acc[nf][1], acc[nf][2], acc[nf][3],
                     a0, a1, a2, a3, b.x, b.y);
        }
    }

    long row0 = r0 + warp * 16 + g;
    long row1 = row0 + 8;
#pragma unroll
    for (int nf = 0; nf < 16; nf++) {
        int n0 = nf * 8 + 2 * tig;
        float b0 = __ldg(bias + n0), b1 = __ldg(bias + n0 + 1);
        if (row0 < rows) {
            float2 o;
            o.x = fmaxf(acc[nf][0] + b0, 0.f);
            o.y = fmaxf(acc[nf][1] + b1, 0.f);
            *(float2*)(out + row0 * HID + n0) = o;
        }
        if (row1 < rows) {
            float2 o;
            o.x = fmaxf(acc[nf][2] + b0, 0.f);
            o.y = fmaxf(acc[nf][3] + b1, 0.f);
            *(float2*)(out + row1 * HID + n0) = o;
        }
    }
}

// segment sum into pool[g][coloff..] + counts
__global__ void k_pool(const float* __restrict__ feat, const int* __restrict__ seg,
                       float* __restrict__ pool, float* __restrict__ cnt,
                       int coloff4, int cntoff, int n) {
    long gid = (long)blockIdx.x * blockDim.x + threadIdx.x;
    int i = (int)(gid >> 5), c = (int)(gid & 31);
    if (i >= n) return;
    int g = seg[i];
    float4 v = ((const float4*)feat)[(long)i * HF4 + c];
    red_add_v4(((float4*)pool) + (long)g * 64 + coloff4 + c, v);
    if (c == 0) atomicAdd(cnt + cntoff + g, 1.f);
}

__global__ void k_readout(const float* __restrict__ pool, const float* __restrict__ cnt,
                          const float* __restrict__ r1w, const float* __restrict__ r1b,
                          const float* __restrict__ r2w, const float* __restrict__ r2b,
                          float* __restrict__ out) {
    __shared__ float x[256];
    __shared__ float redbuf[128];
    int g = blockIdx.x, tid = threadIdx.x;
    float cn = fmaxf(cnt[g], 1.f);
    float ce = fmaxf(cnt[NB + g], 1.f);
    x[tid]       = pool[g * 256 + tid] / cn;
    x[128 + tid] = pool[g * 256 + 128 + tid] / ce;
    __syncthreads();
    float a = r1b[tid];
#pragma unroll 8
    for (int k = 0; k < 256; k++) a += x[k] * r1w[k * 128 + tid];
    float sig = 1.f / (1.f + expf(-a));
    float p = a * sig * r2w[tid];
    redbuf[tid] = p;
    __syncthreads();
    for (int s = 64; s > 0; s >>= 1) {
        if (tid < s) redbuf[tid] += redbuf[tid + s];
        __syncthreads();
    }
    if (tid == 0) out[g] = redbuf[0] + r2b[0];
}

// ---------------- launch ----------------
static inline int cdiv(long a, long b) { return (int)((a + b - 1) / b); }

extern "C" void kernel_launch(void* const* d_in, const int* in_sizes, int n_in,
                              void* d_out, int out_size) {
    const int*   z    = (const int*)  d_in[0];
    const float* d    = (const float*)d_in[1];
    const int*   src  = (const int*)  d_in[2];
    const int*   dst  = (const int*)  d_in[3];
    const int*   lsrc = (const int*)  d_in[4];
    const int*   ldst = (const int*)  d_in[5];
    const int*   ng   = (const int*)  d_in[6];
    const int*   eg   = (const int*)  d_in[7];
    const float* emb  = (const float*)d_in[8];
    const float* epw  = (const float*)d_in[9];
    const float* epb  = (const float*)d_in[10];
    const float* gW   = (const float*)d_in[11];
    const float* gb   = (const float*)d_in[12];
    const float* lgW  = (const float*)d_in[13];
    const float* lgb  = (const float*)d_in[14];
    const float* r1w  = (const float*)d_in[15];
    const float* r1b  = (const float*)d_in[16];
    const float* r2w  = (const float*)d_in[17];
    const float* r2b  = (const float*)d_in[18];
    float* out = (float*)d_out;

    float *p_h, *p_aggN, *p_e, *p_aggE, *p_degN, *p_degE, *p_Wt, *p_pool, *p_cnt;
    cudaGetSymbolAddress((void**)&p_h,    g_h);
    cudaGetSymbolAddress((void**)&p_aggN, g_aggN);
    cudaGetSymbolAddress((void**)&p_e,    g_e);
    cudaGetSymbolAddress((void**)&p_aggE, g_aggE);
    cudaGetSymbolAddress((void**)&p_degN, g_degN);
    cudaGetSymbolAddress((void**)&p_degE, g_degE);
    cudaGetSymbolAddress((void**)&p_Wt,   g_Wt);
    cudaGetSymbolAddress((void**)&p_pool, g_pool);
    cudaGetSymbolAddress((void**)&p_cnt,  g_cnt);

    // per-layer fragment tables (float2 units!)
    const float2* wtL[6];
    for (int l = 0; l < 6; l++) wtL[l] = (const float2*)p_Wt + (long)l * WT_LAYER;

    const int T = 256;
    const long aggE4 = (long)NEDGES * 32;   // float4 count
    const long aggN4 = (long)NNODES * 32;

    // fragment-ordered weights for all 6 layers
    k_wt<<<cdiv(6 * WT_LAYER, T), T>>>(gW, lgW, p_Wt);
    // ---- line graph ----
    k_zero<<<cdiv(2 * NEDGES / 4, T), T>>>(p_degE, 2 * NEDGES / 4);
    k_deg<<<cdiv(NEDGES2, T), T>>>(lsrc, ldst, p_degE, NEDGES, NEDGES2);
    k_zero<<<cdiv(aggE4, T), T>>>(p_aggE, aggE4);
    k_scatter_e0<<<cdiv((long)NEDGES2 * 32, T), T>>>(d, epw, epb, p_degE,
                                                     lsrc, ldst, p_aggE, NEDGES2);
    k_gemm_tc<<<cdiv(NEDGES, 64), 128>>>(p_aggE, p_degE + NEDGES, wtL[3],
                                         lgb, p_e, NEDGES);
    for (int l = 1; l < NLAYERS; l++) {
        k_zero<<<cdiv(aggE4, T), T>>>(p_aggE, aggE4);
        k_scatter<<<cdiv((long)NEDGES2 * 32, T), T>>>(p_e, p_degE, lsrc, ldst, p_aggE, NEDGES2);
        k_gemm_tc<<<cdiv(NEDGES, 64), 128>>>(p_aggE, p_degE + NEDGES, wtL[3 + l],
                                             lgb + (long)l * HID, p_e, NEDGES);
    }
    // ---- node graph ----
    k_zero<<<cdiv(2 * NNODES / 4, T), T>>>(p_degN, 2 * NNODES / 4);
    k_deg<<<cdiv(NEDGES, T), T>>>(src, dst, p_degN, NNODES, NEDGES);
    k_zero<<<cdiv(aggN4, T), T>>>(p_aggN, aggN4);
    k_scatter_h0<<<cdiv((long)NEDGES * 32, T), T>>>(z, emb, p_degN, src, dst, p_aggN, NEDGES);
    k_gemm_tc<<<cdiv(NNODES, 64), 128>>>(p_aggN, p_degN + NNODES, wtL[0],
                                         gb, p_h, NNODES);
    for (int l = 1; l < NLAYERS; l++) {
        k_zero<<<cdiv(aggN4, T), T>>>(p_aggN, aggN4);
        k_scatter<<<cdiv((long)NEDGES * 32, T), T>>>(p_h, p_degN, src, dst, p_aggN, NEDGES);
        k_gemm_tc<<<cdiv(NNODES, 64), 128>>>(p_aggN, p_degN + NNODES, wtL[l],
                                             gb + (long)l * HID, p_h, NNODES);
    }
    // ---- pooling + readout ----
    k_zero<<<cdiv(NB * 2 * HID / 4, T), T>>>(p_pool, NB * 2 * HID / 4);
    k_zero<<<1, 32>>>(p_cnt, 2 * NB / 4);
    k_pool<<<cdiv(aggN4, T), T>>>(p_h, ng, p_pool, p_cnt, 0, 0, NNODES);
    k_pool<<<cdiv(aggE4, T), T>>>(p_e, eg, p_pool, p_cnt, 32, NB, NEDGES);
    k_readout<<<NB, 128>>>(p_pool, p_cnt, r1w, r1b, r2w, r2b, out);
}

// round 5
// speedup vs baseline: 1.7202x; 1.3181x over previous
#include <cuda_runtime.h>
#include <math.h>
#include <stdint.h>

// ---------------- problem constants ----------------
#define NNODES   100000
#define NEDGES   600000
#define NEDGES2  1500000
#define HID      128
#define HF4      32
#define NB       64
#define WT_LAYER 8192   // float2 per layer (16 ks * 16 nf * 32 lanes)
#define SCAN_BS  1024

// ---------------- scratch ----------------
__device__ float g_h   [(size_t)NNODES * HID];
__device__ float g_aggN[(size_t)NNODES * HID];
__device__ float g_e   [(size_t)NEDGES * HID];
__device__ float g_aggE[(size_t)NEDGES * HID];

struct ZB {                       // zeroed in one kernel each launch
    int degN[2 * NNODES];         // [out | in]
    int degE[2 * NEDGES];
    int cnt [2 * NB];             // [node counts | edge counts]
    float pool[NB * 256];         // [B][2H]
};
__device__ ZB  g_zb;
__device__ int g_offN[NNODES];
__device__ int g_curN[NNODES];
__device__ int g_offE[NEDGES];
__device__ int g_curE[NEDGES];
__device__ int g_csrN[NEDGES];    // src node per (dst-sorted) edge
__device__ int g_csrE[NEDGES2];   // src edge per (dst-sorted) line-edge
__device__ int g_bsum[SCAN_BS];
__device__ float g_Wt[6 * WT_LAYER * 2];

// ---------------- helpers ----------------
__device__ __forceinline__ void red_add_v2(float* addr, float x, float y) {
    asm volatile("red.global.add.v2.f32 [%0], {%1,%2};"
                 :: "l"(addr), "f"(x), "f"(y) : "memory");
}
__device__ __forceinline__ uint32_t f2tf32(float f) {
    uint32_t r;
    asm("cvt.rna.tf32.f32 %0, %1;" : "=r"(r) : "f"(f));
    return r;
}
__device__ __forceinline__ void mma_tf32(float& c0, float& c1, float& c2, float& c3,
                                         uint32_t a0, uint32_t a1, uint32_t a2, uint32_t a3,
                                         uint32_t b0, uint32_t b1) {
    asm volatile("mma.sync.aligned.m16n8k8.row.col.f32.tf32.tf32.f32 "
                 "{%0,%1,%2,%3}, {%4,%5,%6,%7}, {%8,%9}, {%0,%1,%2,%3};"
                 : "+f"(c0), "+f"(c1), "+f"(c2), "+f"(c3)
                 : "r"(a0), "r"(a1), "r"(a2), "r"(a3), "r"(b0), "r"(b1));
}
__device__ __forceinline__ float rsdeg_i(int d) {
    return rsqrtf(fmaxf((float)d, 1.f));
}

// ---------------- small kernels ----------------
__global__ void k_zero_all() {
    long n4 = sizeof(ZB) / 16;
    float4* p = (float4*)&g_zb;
    long i = (long)blockIdx.x * blockDim.x + threadIdx.x;
    if (i < n4) p[i] = make_float4(0.f, 0.f, 0.f, 0.f);
}

__global__ void k_wt(const float* __restrict__ gW, const float* __restrict__ lgW,
                     float* __restrict__ Wt) {
    int idx = blockIdx.x * blockDim.x + threadIdx.x;
    if (idx >= 6 * WT_LAYER) return;
    int layer = idx >> 13;
    int rem = idx & 8191;
    int ks = rem >> 9;
    int rem2 = rem & 511;
    int nf = rem2 >> 5, lane = rem2 & 31;
    int g = lane >> 2, tig = lane & 3;
    int n = nf * 8 + g, k = ks * 8 + tig;
    const float* W = (layer < 3) ? (gW + (long)layer * 16384)
                                 : (lgW + (long)(layer - 3) * 16384);
    Wt[(long)idx * 2 + 0] = __uint_as_float(f2tf32(__ldg(W + k * HID + n)));
    Wt[(long)idx * 2 + 1] = __uint_as_float(f2tf32(__ldg(W + (k + 4) * HID + n)));
}

__global__ void k_deg(const int* __restrict__ s, const int* __restrict__ t,
                      int* deg, int noff, int n) {
    int i = blockIdx.x * blockDim.x + threadIdx.x;
    if (i < n) {
        atomicAdd(deg + s[i], 1);
        atomicAdd(deg + noff + t[i], 1);
    }
}

__global__ void k_cnt(const int* __restrict__ seg, int* __restrict__ cnt,
                      int cntoff, int n) {
    __shared__ int h[NB];
    int t = threadIdx.x;
    if (t < NB) h[t] = 0;
    __syncthreads();
    int i = blockIdx.x * blockDim.x + t;
    if (i < n) atomicAdd(h + seg[i], 1);
    __syncthreads();
    if (t < NB && h[t]) atomicAdd(cnt + cntoff + t, h[t]);
}

// exclusive scan of deg -> off (3 kernels)
__global__ void k_scan1(const int* __restrict__ deg, int* __restrict__ off,
                        int* __restrict__ bsum, int n) {
    __shared__ int sh[SCAN_BS];
    int t = threadIdx.x;
    int i = blockIdx.x * SCAN_BS + t;
    int v = (i < n) ? deg[i] : 0;
    sh[t] = v;
    __syncthreads();
    for (int s = 1; s < SCAN_BS; s <<= 1) {
        int add = (t >= s) ? sh[t - s] : 0;
        __syncthreads();
        sh[t] += add;
        __syncthreads();
    }
    if (i < n) off[i] = sh[t] - v;
    if (t == SCAN_BS - 1) bsum[blockIdx.x] = sh[t];
}
__global__ void k_scan2(int* bsum, int nb) {   // single block, nb <= 1024
    __shared__ int sh[SCAN_BS];
    int t = threadIdx.x;
    int v = (t < nb) ? bsum[t] : 0;
    sh[t] = v;
    __syncthreads();
    for (int s = 1; s < SCAN_BS; s <<= 1) {
        int add = (t >= s) ? sh[t - s] : 0;
        __syncthreads();
        sh[t] += add;
        __syncthreads();
    }
    if (t < nb) bsum[t] = sh[t] - v;
}
__global__ void k_scan3(int* __restrict__ off, const int* __restrict__ bsum,
                        int* __restrict__ cur, int n) {
    int i = blockIdx.x * blockDim.x + threadIdx.x;
    if (i < n) {
        int o = off[i] + bsum[i >> 10];
        off[i] = o;
        cur[i] = o;
    }
}

__global__ void k_fill(const int* __restrict__ s, const int* __restrict__ t,
                       int* __restrict__ cur, int* __restrict__ csr, int n) {
    int i = blockIdx.x * blockDim.x + threadIdx.x;
    if (i < n) {
        int p = atomicAdd(cur + t[i], 1);
        csr[p] = s[i];
    }
}

// ---------------- CSR gather: agg[r] = rsdeg_in(r) * sum_{s in N(r)} f(s)*rsdeg_out(s)
// MODE 0: f = feat[s];  MODE 1: f = d[s]*ep_w + ep_b;  MODE 2: f = emb[z[s]]
template<int MODE>
__global__ void k_gather(const float* __restrict__ feat, const int* __restrict__ z,
                         const float* __restrict__ emb, const float* __restrict__ epw,
                         const float* __restrict__ epb,
                         const int* __restrict__ dego, const int* __restrict__ degi,
                         const int* __restrict__ off, const int* __restrict__ csr,
                         float* __restrict__ agg, int rows) {
    long gw = ((long)blockIdx.x * blockDim.x + threadIdx.x) >> 5;
    int lane = threadIdx.x & 31;
    if (gw >= rows) return;
    int r = (int)gw;
    int beg = __ldg(off + r), dg = __ldg(degi + r);
    float4 acc = make_float4(0.f, 0.f, 0.f, 0.f);
    float4 wv, bv;
    if (MODE == 1) { wv = ((const float4*)epw)[lane]; bv = ((const float4*)epb)[lane]; }
    for (int j = beg; j < beg + dg; j++) {
        int s = __ldg(csr + j);
        float sc = rsdeg_i(__ldg(dego + s));
        if (MODE == 0) {
            float4 v = __ldg((const float4*)feat + (long)s * HF4 + lane);
            acc.x += v.x * sc; acc.y += v.y * sc; acc.z += v.z * sc; acc.w += v.w * sc;
        } else if (MODE == 1) {
            float dv = __ldg(feat + s) * sc;   // feat == d
            acc.x += dv * wv.x + bv.x * sc;
            acc.y += dv * wv.y + bv.y * sc;
            acc.z += dv * wv.z + bv.z * sc;
            acc.w += dv * wv.w + bv.w * sc;
        } else {
            int zi = __ldg(z + s);
            float4 v = __ldg((const float4*)emb + (long)zi * HF4 + lane);
            acc.x += v.x * sc; acc.y += v.y * sc; acc.z += v.z * sc; acc.w += v.w * sc;
        }
    }
    float si = rsdeg_i(dg);
    acc.x *= si; acc.y *= si; acc.z *= si; acc.w *= si;
    ((float4*)agg)[(long)r * HF4 + lane] = acc;
}

// ---------------- tensor-core GEMM: relu(X @ W + b) ------------------------
// EPI 0: store rows to out.   EPI 1: red.add into pool[seg[row]*256+coloff+n]
#define XS_STRIDE 132
template<int EPI>
__global__ void __launch_bounds__(128)
k_gemm_tc(const float* __restrict__ X, const float2* __restrict__ Wt,
          const float* __restrict__ bias, float* __restrict__ out,
          const int* __restrict__ seg, float* __restrict__ pool, int coloff,
          int rows) {
    __shared__ __align__(16) uint32_t Xs[64 * XS_STRIDE];
    int tid = threadIdx.x;
    int warp = tid >> 5, lane = tid & 31;
    int g = lane >> 2, tig = lane & 3;
    long r0 = (long)blockIdx.x * 64;

    {
        const float4* X4 = (const float4*)X;
        for (int i = tid; i < 64 * 32; i += 128) {
            int rl = i >> 5, c = i & 31;
            long r = r0 + rl;
            float4 v = make_float4(0.f, 0.f, 0.f, 0.f);
            if (r < rows) v = X4[r * HF4 + c];
            uint32_t* p = Xs + rl * XS_STRIDE + c * 4;
            p[0] = f2tf32(v.x); p[1] = f2tf32(v.y);
            p[2] = f2tf32(v.z); p[3] = f2tf32(v.w);
        }
    }
    __syncthreads();

    float acc[16][4];
#pragma unroll
    for (int nf = 0; nf < 16; nf++)
#pragma unroll
        for (int j = 0; j < 4; j++) acc[nf][j] = 0.f;

    const uint32_t* xa = Xs + (warp * 16 + g) * XS_STRIDE + tig;
    const uint2* wt = ((const uint2*)Wt) + lane;
#pragma unroll 4
    for (int ks = 0; ks < 16; ks++) {
        int k0 = ks * 8;
        uint32_t a0 = xa[k0];
        uint32_t a1 = xa[8 * XS_STRIDE + k0];
        uint32_t a2 = xa[k0 + 4];
        uint32_t a3 = xa[8 * XS_STRIDE + k0 + 4];
#pragma unroll
        for (int nf = 0; nf < 16; nf++) {
            uint2 b = __ldg(wt + (ks * 16 + nf) * 32);
            mma_tf32(acc[nf][0], acc[nf][1], acc[nf][2], acc[nf][3],
                     a0, a1, a2, a3, b.x, b.y);
        }
    }

    long row0 = r0 + warp * 16 + g;
    long row1 = row0 + 8;
    int seg0 = 0, seg1 = 0;
    if (EPI == 1) {
        if (row0 < rows) seg0 = __ldg(seg + row0);
        if (row1 < rows) seg1 = __ldg(seg + row1);
    }
#pragma unroll
    for (int nf = 0; nf < 16; nf++) {
        int n0 = nf * 8 + 2 * tig;
        float b0 = __ldg(bias + n0), b1 = __ldg(bias + n0 + 1);
        if (row0 < rows) {
            float ox = fmaxf(acc[nf][0] + b0, 0.f);
            float oy = fmaxf(acc[nf][1] + b1, 0.f);
            if (EPI == 0) *(float2*)(out + row0 * HID + n0) = make_float2(ox, oy);
            else red_add_v2(pool + (long)seg0 * 256 + coloff + n0, ox, oy);
        }
        if (row1 < rows) {
            float ox = fmaxf(acc[nf][2] + b0, 0.f);
            float oy = fmaxf(acc[nf][3] + b1, 0.f);
            if (EPI == 0) *(float2*)(out + row1 * HID + n0) = make_float2(ox, oy);
            else red_add_v2(pool + (long)seg1 * 256 + coloff + n0, ox, oy);
        }
    }
}

// final MLP
__global__ void k_readout(const float* __restrict__ pool, const int* __restrict__ cnt,
                          const float* __restrict__ r1w, const float* __restrict__ r1b,
                          const float* __restrict__ r2w, const float* __restrict__ r2b,
                          float* __restrict__ out) {
    __shared__ float x[256];
    __shared__ float redbuf[128];
    int g = blockIdx.x, tid = threadIdx.x;
    float cn = fmaxf((float)cnt[g], 1.f);
    float ce = fmaxf((float)cnt[NB + g], 1.f);
    x[tid]       = pool[g * 256 + tid] / cn;
    x[128 + tid] = pool[g * 256 + 128 + tid] / ce;
    __syncthreads();
    float a = r1b[tid];
#pragma unroll 8
    for (int k = 0; k < 256; k++) a += x[k] * r1w[k * 128 + tid];
    float sig = 1.f / (1.f + expf(-a));
    float p = a * sig * r2w[tid];
    redbuf[tid] = p;
    __syncthreads();
    for (int s = 64; s > 0; s >>= 1) {
        if (tid < s) redbuf[tid] += redbuf[tid + s];
        __syncthreads();
    }
    if (tid == 0) out[g] = redbuf[0] + r2b[0];
}

// ---------------- launch ----------------
static inline int cdiv(long a, long b) { return (int)((a + b - 1) / b); }

extern "C" void kernel_launch(void* const* d_in, const int* in_sizes, int n_in,
                              void* d_out, int out_size) {
    const int*   z    = (const int*)  d_in[0];
    const float* d    = (const float*)d_in[1];
    const int*   src  = (const int*)  d_in[2];
    const int*   dst  = (const int*)  d_in[3];
    const int*   lsrc = (const int*)  d_in[4];
    const int*   ldst = (const int*)  d_in[5];
    const int*   ng   = (const int*)  d_in[6];
    const int*   eg   = (const int*)  d_in[7];
    const float* emb  = (const float*)d_in[8];
    const float* epw  = (const float*)d_in[9];
    const float* epb  = (const float*)d_in[10];
    const float* gW   = (const float*)d_in[11];
    const float* gb   = (const float*)d_in[12];
    const float* lgW  = (const float*)d_in[13];
    const float* lgb  = (const float*)d_in[14];
    const float* r1w  = (const float*)d_in[15];
    const float* r1b  = (const float*)d_in[16];
    const float* r2w  = (const float*)d_in[17];
    const float* r2b  = (const float*)d_in[18];
    float* out = (float*)d_out;

    float *p_h, *p_aggN, *p_e, *p_aggE, *p_Wt;
    int *p_offN, *p_curN, *p_offE, *p_curE, *p_csrN, *p_csrE, *p_bsum;
    ZB* p_zb;
    cudaGetSymbolAddress((void**)&p_h,    g_h);
    cudaGetSymbolAddress((void**)&p_aggN, g_aggN);
    cudaGetSymbolAddress((void**)&p_e,    g_e);
    cudaGetSymbolAddress((void**)&p_aggE, g_aggE);
    cudaGetSymbolAddress((void**)&p_zb,   g_zb);
    cudaGetSymbolAddress((void**)&p_offN, g_offN);
    cudaGetSymbolAddress((void**)&p_curN, g_curN);
    cudaGetSymbolAddress((void**)&p_offE, g_offE);
    cudaGetSymbolAddress((void**)&p_curE, g_curE);
    cudaGetSymbolAddress((void**)&p_csrN, g_csrN);
    cudaGetSymbolAddress((void**)&p_csrE, g_csrE);
    cudaGetSymbolAddress((void**)&p_bsum, g_bsum);
    cudaGetSymbolAddress((void**)&p_Wt,   g_Wt);

    int* p_degNo = p_zb->degN;           // device pointers: member offsets are
    int* p_degNi = p_zb->degN + NNODES;  // computed on the host side of the
    int* p_degEo = p_zb->degE;           // device address — plain arithmetic
    int* p_degEi = p_zb->degE + NEDGES;
    int* p_cnt   = p_zb->cnt;
    float* p_pool = p_zb->pool;

    const float2* wtL[6];
    for (int l = 0; l < 6; l++) wtL[l] = (const float2*)p_Wt + (long)l * WT_LAYER;

    const int T = 256;

    // zero all small state (degrees, counts, pool)
    k_zero_all<<<cdiv(sizeof(ZB) / 16, T), T>>>();
    k_wt<<<cdiv(6 * WT_LAYER, T), T>>>(gW, lgW, p_Wt);
    k_cnt<<<cdiv(NNODES, T), T>>>(ng, p_cnt, 0, NNODES);
    k_cnt<<<cdiv(NEDGES, T), T>>>(eg, p_cnt, NB, NEDGES);

    // ---- CSR build: line graph ----
    k_deg<<<cdiv(NEDGES2, T), T>>>(lsrc, ldst, p_degEo, NEDGES, NEDGES2);
    k_scan1<<<cdiv(NEDGES, SCAN_BS), SCAN_BS>>>(p_degEi, p_offE, p_bsum, NEDGES);
    k_scan2<<<1, SCAN_BS>>>(p_bsum, cdiv(NEDGES, SCAN_BS));
    k_scan3<<<cdiv(NEDGES, T), T>>>(p_offE, p_bsum, p_curE, NEDGES);
    k_fill<<<cdiv(NEDGES2, T), T>>>(lsrc, ldst, p_curE, p_csrE, NEDGES2);
    // ---- CSR build: node graph ----
    k_deg<<<cdiv(NEDGES, T), T>>>(src, dst, p_degNo, NNODES, NEDGES);
    k_scan1<<<cdiv(NNODES, SCAN_BS), SCAN_BS>>>(p_degNi, p_offN, p_bsum, NNODES);
    k_scan2<<<1, SCAN_BS>>>(p_bsum, cdiv(NNODES, SCAN_BS));
    k_scan3<<<cdiv(NNODES, T), T>>>(p_offN, p_bsum, p_curN, NNODES);
    k_fill<<<cdiv(NEDGES, T), T>>>(src, dst, p_curN, p_csrN, NEDGES);

    const long gwE = (long)NEDGES * 32, gwN = (long)NNODES * 32;

    // ---- line graph layers ----
    k_gather<1><<<cdiv(gwE, T), T>>>(d, nullptr, nullptr, epw, epb,
                                     p_degEo, p_degEi, p_offE, p_csrE, p_aggE, NEDGES);
    k_gemm_tc<0><<<cdiv(NEDGES, 64), 128>>>(p_aggE, wtL[3], lgb, p_e,
                                            nullptr, nullptr, 0, NEDGES);
    k_gather<0><<<cdiv(gwE, T), T>>>(p_e, nullptr, nullptr, nullptr, nullptr,
                                     p_degEo, p_degEi, p_offE, p_csrE, p_aggE, NEDGES);
    k_gemm_tc<0><<<cdiv(NEDGES, 64), 128>>>(p_aggE, wtL[4], lgb + HID, p_e,
                                            nullptr, nullptr, 0, NEDGES);
    k_gather<0><<<cdiv(gwE, T), T>>>(p_e, nullptr, nullptr, nullptr, nullptr,
                                     p_degEo, p_degEi, p_offE, p_csrE, p_aggE, NEDGES);
    k_gemm_tc<1><<<cdiv(NEDGES, 64), 128>>>(p_aggE, wtL[5], lgb + 2 * HID, nullptr,
                                            eg, p_pool, 128, NEDGES);
    // ---- node graph layers ----
    k_gather<2><<<cdiv(gwN, T), T>>>(nullptr, z, emb, nullptr, nullptr,
                                     p_degNo, p_degNi, p_offN, p_csrN, p_aggN, NNODES);
    k_gemm_tc<0><<<cdiv(NNODES, 64), 128>>>(p_aggN, wtL[0], gb, p_h,
                                            nullptr, nullptr, 0, NNODES);
    k_gather<0><<<cdiv(gwN, T), T>>>(p_h, nullptr, nullptr, nullptr, nullptr,
                                     p_degNo, p_degNi, p_offN, p_csrN, p_aggN, NNODES);
    k_gemm_tc<0><<<cdiv(NNODES, 64), 128>>>(p_aggN, wtL[1], gb + HID, p_h,
                                            nullptr, nullptr, 0, NNODES);
    k_gather<0><<<cdiv(gwN, T), T>>>(p_h, nullptr, nullptr, nullptr, nullptr,
                                     p_degNo, p_degNi, p_offN, p_csrN, p_aggN, NNODES);
    k_gemm_tc<1><<<cdiv(NNODES, 64), 128>>>(p_aggN, wtL[2], gb + 2 * HID, nullptr,
                                            ng, p_pool, 0, NNODES);

    // ---- readout ----
    k_readout<<<NB, 128>>>(p_pool, p_cnt, r1w, r1b, r2w, r2b, out);
}

// round 7
// speedup vs baseline: 2.0311x; 1.1807x over previous
#include <cuda_runtime.h>
#include <math.h>
#include <stdint.h>

// ---------------- problem constants ----------------
#define NNODES   100000
#define NEDGES   600000
#define NEDGES2  1500000
#define HID      128
#define HF4      32
#define NB       64
#define WT_LAYER 8192   // float2 per layer (16 ks * 16 nf * 32 lanes)
#define SCAN_BS  1024

// ---------------- scratch (ping-pong feature buffers) ----------------------
__device__ float g_hA[(size_t)NNODES * HID];
__device__ float g_hB[(size_t)NNODES * HID];
__device__ float g_eA[(size_t)NEDGES * HID];
__device__ float g_eB[(size_t)NEDGES * HID];

struct ZB {                       // zeroed in one kernel each launch
    int degN[2 * NNODES];         // [out | in]
    int degE[2 * NEDGES];
    int cnt [2 * NB];
    float pool[NB * 256];
};
__device__ ZB  g_zb;
__device__ int g_offN[NNODES];
__device__ int g_curN[NNODES];
__device__ int g_offE[NEDGES];
__device__ int g_curE[NEDGES];
__device__ int g_csrN[NEDGES];
__device__ int g_csrE[NEDGES2];
__device__ int g_bsum[SCAN_BS];
__device__ float g_Wt[6 * WT_LAYER * 2];

// ---------------- helpers ----------------
__device__ __forceinline__ void red_add_v2(float* addr, float x, float y) {
    asm volatile("red.global.add.v2.f32 [%0], {%1,%2};"
                 :: "l"(addr), "f"(x), "f"(y) : "memory");
}
__device__ __forceinline__ uint32_t f2tf32(float f) {
    uint32_t r;
    asm("cvt.rna.tf32.f32 %0, %1;" : "=r"(r) : "f"(f));
    return r;
}
__device__ __forceinline__ void mma_tf32(float& c0, float& c1, float& c2, float& c3,
                                         uint32_t a0, uint32_t a1, uint32_t a2, uint32_t a3,
                                         uint32_t b0, uint32_t b1) {
    asm volatile("mma.sync.aligned.m16n8k8.row.col.f32.tf32.tf32.f32 "
                 "{%0,%1,%2,%3}, {%4,%5,%6,%7}, {%8,%9}, {%0,%1,%2,%3};"
                 : "+f"(c0), "+f"(c1), "+f"(c2), "+f"(c3)
                 : "r"(a0), "r"(a1), "r"(a2), "r"(a3), "r"(b0), "r"(b1));
}
__device__ __forceinline__ float rsdeg_i(int d) {
    return rsqrtf(fmaxf((float)d, 1.f));
}

// ---------------- small kernels ----------------
__global__ void k_zero_all() {
    long n4 = sizeof(ZB) / 16;
    float4* p = (float4*)&g_zb;
    long i = (long)blockIdx.x * blockDim.x + threadIdx.x;
    if (i < n4) p[i] = make_float4(0.f, 0.f, 0.f, 0.f);
}

__global__ void k_wt(const float* __restrict__ gW, const float* __restrict__ lgW,
                     float* __restrict__ Wt) {
    int idx = blockIdx.x * blockDim.x + threadIdx.x;
    if (idx >= 6 * WT_LAYER) return;
    int layer = idx >> 13;
    int rem = idx & 8191;
    int ks = rem >> 9;
    int rem2 = rem & 511;
    int nf = rem2 >> 5, lane = rem2 & 31;
    int g = lane >> 2, tig = lane & 3;
    int n = nf * 8 + g, k = ks * 8 + tig;
    const float* W = (layer < 3) ? (gW + (long)layer * 16384)
                                 : (lgW + (long)(layer - 3) * 16384);
    Wt[(long)idx * 2 + 0] = __uint_as_float(f2tf32(__ldg(W + k * HID + n)));
    Wt[(long)idx * 2 + 1] = __uint_as_float(f2tf32(__ldg(W + (k + 4) * HID + n)));
}

__global__ void k_deg(const int* __restrict__ s, const int* __restrict__ t,
                      int* deg, int noff, int n) {
    int i = blockIdx.x * blockDim.x + threadIdx.x;
    if (i < n) {
        atomicAdd(deg + s[i], 1);
        atomicAdd(deg + noff + t[i], 1);
    }
}

__global__ void k_cnt(const int* __restrict__ seg, int* __restrict__ cnt,
                      int cntoff, int n) {
    __shared__ int h[NB];
    int t = threadIdx.x;
    if (t < NB) h[t] = 0;
    __syncthreads();
    int i = blockIdx.x * blockDim.x + t;
    if (i < n) atomicAdd(h + seg[i], 1);
    __syncthreads();
    if (t < NB && h[t]) atomicAdd(cnt + cntoff + t, h[t]);
}

__global__ void k_scan1(const int* __restrict__ deg, int* __restrict__ off,
                        int* __restrict__ bsum, int n) {
    __shared__ int sh[SCAN_BS];
    int t = threadIdx.x;
    int i = blockIdx.x * SCAN_BS + t;
    int v = (i < n) ? deg[i] : 0;
    sh[t] = v;
    __syncthreads();
    for (int s = 1; s < SCAN_BS; s <<= 1) {
        int add = (t >= s) ? sh[t - s] : 0;
        __syncthreads();
        sh[t] += add;
        __syncthreads();
    }
    if (i < n) off[i] = sh[t] - v;
    if (t == SCAN_BS - 1) bsum[blockIdx.x] = sh[t];
}
__global__ void k_scan2(int* bsum, int nb) {
    __shared__ int sh[SCAN_BS];
    int t = threadIdx.x;
    int v = (t < nb) ? bsum[t] : 0;
    sh[t] = v;
    __syncthreads();
    for (int s = 1; s < SCAN_BS; s <<= 1) {
        int add = (t >= s) ? sh[t - s] : 0;
        __syncthreads();
        sh[t] += add;
        __syncthreads();
    }
    if (t < nb) bsum[t] = sh[t] - v;
}
__global__ void k_scan3(int* __restrict__ off, const int* __restrict__ bsum,
                        int* __restrict__ cur, int n) {
    int i = blockIdx.x * blockDim.x + threadIdx.x;
    if (i < n) {
        int o = off[i] + bsum[i >> 10];
        off[i] = o;
        cur[i] = o;
    }
}
__global__ void k_fill(const int* __restrict__ s, const int* __restrict__ t,
                       int* __restrict__ cur, int* __restrict__ csr, int n) {
    int i = blockIdx.x * blockDim.x + threadIdx.x;
    if (i < n) {
        int p = atomicAdd(cur + t[i], 1);
        csr[p] = s[i];
    }
}

// ---------------- fused CSR-gather + tensor-core GEMM ----------------------
// out_row = relu( [ rsdeg_in(r) * sum_{s in N(r)} f(s) * rsdeg_out(s) ] @ W + b )
// MODE 0: f = feat[s];  MODE 1: f = d[s]*ep_w + ep_b;  MODE 2: f = emb[z[s]]
// EPI  0: store rows;   EPI  1: red.add into pool[seg[row]*256 + coloff + n]
// NOTE: 'feat' (gather source) and 'out' must be DISTINCT buffers (ping-pong),
// since other blocks' epilogues run concurrently with this block's gather.
#define XS_STRIDE 132
template<int MODE, int EPI>
__global__ void __launch_bounds__(128)
k_conv(const float* __restrict__ feat, const int* __restrict__ z,
       const float* __restrict__ emb, const float* __restrict__ epw,
       const float* __restrict__ epb,
       const int* __restrict__ dego, const int* __restrict__ degi,
       const int* __restrict__ off, const int* __restrict__ csr,
       const float2* __restrict__ Wt, const float* __restrict__ bias,
       float* __restrict__ out, const int* __restrict__ seg,
       float* __restrict__ pool, int coloff, int rows) {
    __shared__ __align__(16) uint32_t Xs[64 * XS_STRIDE];
    int tid = threadIdx.x;
    int warp = tid >> 5, lane = tid & 31;
    int g = lane >> 2, tig = lane & 3;
    long r0 = (long)blockIdx.x * 64;

    // ---- phase 1: gather A-tile (warp per row, 16 rows per warp) ----
    float4 wv, bv;
    if (MODE == 1) { wv = ((const float4*)epw)[lane]; bv = ((const float4*)epb)[lane]; }
    for (int rl = warp; rl < 64; rl += 4) {
        long r = r0 + rl;
        float4 acc = make_float4(0.f, 0.f, 0.f, 0.f);
        float si = 0.f;
        if (r < rows) {
            int beg = __ldg(off + r), dg = __ldg(degi + r);
            for (int j = beg; j < beg + dg; j++) {
                int s = __ldg(csr + j);
                float sc = rsdeg_i(__ldg(dego + s));
                if (MODE == 0) {
                    float4 v = __ldg((const float4*)feat + (long)s * HF4 + lane);
                    acc.x += v.x * sc; acc.y += v.y * sc;
                    acc.z += v.z * sc; acc.w += v.w * sc;
                } else if (MODE == 1) {
                    float dv = __ldg(feat + s) * sc;   // feat == d
                    acc.x += dv * wv.x + bv.x * sc;
                    acc.y += dv * wv.y + bv.y * sc;
                    acc.z += dv * wv.z + bv.z * sc;
                    acc.w += dv * wv.w + bv.w * sc;
                } else {
                    int zi = __ldg(z + s);
                    float4 v = __ldg((const float4*)emb + (long)zi * HF4 + lane);
                    acc.x += v.x * sc; acc.y += v.y * sc;
                    acc.z += v.z * sc; acc.w += v.w * sc;
                }
            }
            si = rsdeg_i(dg);
        }
        uint32_t* p = Xs + rl * XS_STRIDE + lane * 4;
        p[0] = f2tf32(acc.x * si); p[1] = f2tf32(acc.y * si);
        p[2] = f2tf32(acc.z * si); p[3] = f2tf32(acc.w * si);
    }
    __syncthreads();

    // ---- phase 2: 64x128 @ 128x128 tf32 MMA ----
    float acc[16][4];
#pragma unroll
    for (int nf = 0; nf < 16; nf++)
#pragma unroll
        for (int j = 0; j < 4; j++) acc[nf][j] = 0.f;

    const uint32_t* xa = Xs + (warp * 16 + g) * XS_STRIDE + tig;
    const uint2* wt = ((const uint2*)Wt) + lane;
#pragma unroll 4
    for (int ks = 0; ks < 16; ks++) {
        int k0 = ks * 8;
        uint32_t a0 = xa[k0];
        uint32_t a1 = xa[8 * XS_STRIDE + k0];
        uint32_t a2 = xa[k0 + 4];
        uint32_t a3 = xa[8 * XS_STRIDE + k0 + 4];
#pragma unroll
        for (int nf = 0; nf < 16; nf++) {
            uint2 b = __ldg(wt + (ks * 16 + nf) * 32);
            mma_tf32(acc[nf][0], acc[nf][1], acc[nf][2], acc[nf][3],
                     a0, a1, a2, a3, b.x, b.y);
        }
    }

    long row0 = r0 + warp * 16 + g;
    long row1 = row0 + 8;
    int seg0 = 0, seg1 = 0;
    if (EPI == 1) {
        if (row0 < rows) seg0 = __ldg(seg + row0);
        if (row1 < rows) seg1 = __ldg(seg + row1);
    }
#pragma unroll
    for (int nf = 0; nf < 16; nf++) {
        int n0 = nf * 8 + 2 * tig;
        float b0 = __ldg(bias + n0), b1 = __ldg(bias + n0 + 1);
        if (row0 < rows) {
            float ox = fmaxf(acc[nf][0] + b0, 0.f);
            float oy = fmaxf(acc[nf][1] + b1, 0.f);
            if (EPI == 0) *(float2*)(out + row0 * HID + n0) = make_float2(ox, oy);
            else red_add_v2(pool + (long)seg0 * 256 + coloff + n0, ox, oy);
        }
        if (row1 < rows) {
            float ox = fmaxf(acc[nf][2] + b0, 0.f);
            float oy = fmaxf(acc[nf][3] + b1, 0.f);
            if (EPI == 0) *(float2*)(out + row1 * HID + n0) = make_float2(ox, oy);
            else red_add_v2(pool + (long)seg1 * 256 + coloff + n0, ox, oy);
        }
    }
}

// final MLP
__global__ void k_readout(const float* __restrict__ pool, const int* __restrict__ cnt,
                          const float* __restrict__ r1w, const float* __restrict__ r1b,
                          const float* __restrict__ r2w, const float* __restrict__ r2b,
                          float* __restrict__ out) {
    __shared__ float x[256];
    __shared__ float redbuf[128];
    int g = blockIdx.x, tid = threadIdx.x;
    float cn = fmaxf((float)cnt[g], 1.f);
    float ce = fmaxf((float)cnt[NB + g], 1.f);
    x[tid]       = pool[g * 256 + tid] / cn;
    x[128 + tid] = pool[g * 256 + 128 + tid] / ce;
    __syncthreads();
    float a = r1b[tid];
#pragma unroll 8
    for (int k = 0; k < 256; k++) a += x[k] * r1w[k * 128 + tid];
    float sig = 1.f / (1.f + expf(-a));
    float p = a * sig * r2w[tid];
    redbuf[tid] = p;
    __syncthreads();
    for (int s = 64; s > 0; s >>= 1) {
        if (tid < s) redbuf[tid] += redbuf[tid + s];
        __syncthreads();
    }
    if (tid == 0) out[g] = redbuf[0] + r2b[0];
}

// ---------------- launch ----------------
static inline int cdiv(long a, long b) { return (int)((a + b - 1) / b); }

extern "C" void kernel_launch(void* const* d_in, const int* in_sizes, int n_in,
                              void* d_out, int out_size) {
    const int*   z    = (const int*)  d_in[0];
    const float* d    = (const float*)d_in[1];
    const int*   src  = (const int*)  d_in[2];
    const int*   dst  = (const int*)  d_in[3];
    const int*   lsrc = (const int*)  d_in[4];
    const int*   ldst = (const int*)  d_in[5];
    const int*   ng   = (const int*)  d_in[6];
    const int*   eg   = (const int*)  d_in[7];
    const float* emb  = (const float*)d_in[8];
    const float* epw  = (const float*)d_in[9];
    const float* epb  = (const float*)d_in[10];
    const float* gW   = (const float*)d_in[11];
    const float* gb   = (const float*)d_in[12];
    const float* lgW  = (const float*)d_in[13];
    const float* lgb  = (const float*)d_in[14];
    const float* r1w  = (const float*)d_in[15];
    const float* r1b  = (const float*)d_in[16];
    const float* r2w  = (const float*)d_in[17];
    const float* r2b  = (const float*)d_in[18];
    float* out = (float*)d_out;

    float *p_hA, *p_hB, *p_eA, *p_eB, *p_Wt;
    int *p_offN, *p_curN, *p_offE, *p_curE, *p_csrN, *p_csrE, *p_bsum;
    ZB* p_zb;
    cudaGetSymbolAddress((void**)&p_hA,   g_hA);
    cudaGetSymbolAddress((void**)&p_hB,   g_hB);
    cudaGetSymbolAddress((void**)&p_eA,   g_eA);
    cudaGetSymbolAddress((void**)&p_eB,   g_eB);
    cudaGetSymbolAddress((void**)&p_zb,   g_zb);
    cudaGetSymbolAddress((void**)&p_offN, g_offN);
    cudaGetSymbolAddress((void**)&p_curN, g_curN);
    cudaGetSymbolAddress((void**)&p_offE, g_offE);
    cudaGetSymbolAddress((void**)&p_curE, g_curE);
    cudaGetSymbolAddress((void**)&p_csrN, g_csrN);
    cudaGetSymbolAddress((void**)&p_csrE, g_csrE);
    cudaGetSymbolAddress((void**)&p_bsum, g_bsum);
    cudaGetSymbolAddress((void**)&p_Wt,   g_Wt);

    int* p_degNo = p_zb->degN;
    int* p_degNi = p_zb->degN + NNODES;
    int* p_degEo = p_zb->degE;
    int* p_degEi = p_zb->degE + NEDGES;
    int* p_cnt   = p_zb->cnt;
    float* p_pool = p_zb->pool;

    const float2* wtL[6];
    for (int l = 0; l < 6; l++) wtL[l] = (const float2*)p_Wt + (long)l * WT_LAYER;

    const int T = 256;

    k_zero_all<<<cdiv(sizeof(ZB) / 16, T), T>>>();
    k_wt<<<cdiv(6 * WT_LAYER, T), T>>>(gW, lgW, p_Wt);

    // ---- CSR build: line graph ----
    k_deg<<<cdiv(NEDGES2, T), T>>>(lsrc, ldst, p_degEo, NEDGES, NEDGES2);
    k_scan1<<<cdiv(NEDGES, SCAN_BS), SCAN_BS>>>(p_degEi, p_offE, p_bsum, NEDGES);
    k_scan2<<<1, SCAN_BS>>>(p_bsum, cdiv(NEDGES, SCAN_BS));
    k_scan3<<<cdiv(NEDGES, T), T>>>(p_offE, p_bsum, p_curE, NEDGES);
    k_fill<<<cdiv(NEDGES2, T), T>>>(lsrc, ldst, p_curE, p_csrE, NEDGES2);
    // ---- CSR build: node graph ----
    k_deg<<<cdiv(NEDGES, T), T>>>(src, dst, p_degNo, NNODES, NEDGES);
    k_scan1<<<cdiv(NNODES, SCAN_BS), SCAN_BS>>>(p_degNi, p_offN, p_bsum, NNODES);
    k_scan2<<<1, SCAN_BS>>>(p_bsum, cdiv(NNODES, SCAN_BS));
    k_scan3<<<cdiv(NNODES, T), T>>>(p_offN, p_bsum, p_curN, NNODES);
    k_fill<<<cdiv(NEDGES, T), T>>>(src, dst, p_curN, p_csrN, NEDGES);

    const int gE = cdiv(NEDGES, 64), gN = cdiv(NNODES, 64);

    // ---- line graph layers (fused gather+gemm, ping-pong e buffers) ----
    k_conv<1, 0><<<gE, 128>>>(d, nullptr, nullptr, epw, epb,
                              p_degEo, p_degEi, p_offE, p_csrE,
                              wtL[3], lgb, p_eA, nullptr, nullptr, 0, NEDGES);
    k_conv<0, 0><<<gE, 128>>>(p_eA, nullptr, nullptr, nullptr, nullptr,
                              p_degEo, p_degEi, p_offE, p_csrE,
                              wtL[4], lgb + HID, p_eB, nullptr, nullptr, 0, NEDGES);
    k_conv<0, 1><<<gE, 128>>>(p_eB, nullptr, nullptr, nullptr, nullptr,
                              p_degEo, p_degEi, p_offE, p_csrE,
                              wtL[5], lgb + 2 * HID, nullptr, eg, p_pool, 128, NEDGES);
    // ---- node graph layers (ping-pong h buffers) ----
    k_conv<2, 0><<<gN, 128>>>(nullptr, z, emb, nullptr, nullptr,
                              p_degNo, p_degNi, p_offN, p_csrN,
                              wtL[0], gb, p_hA, nullptr, nullptr, 0, NNODES);
    k_conv<0, 0><<<gN, 128>>>(p_hA, nullptr, nullptr, nullptr, nullptr,
                              p_degNo, p_degNi, p_offN, p_csrN,
                              wtL[1], gb + HID, p_hB, nullptr, nullptr, 0, NNODES);
    k_conv<0, 1><<<gN, 128>>>(p_hB, nullptr, nullptr, nullptr, nullptr,
                              p_degNo, p_degNi, p_offN, p_csrN,
                              wtL[2], gb + 2 * HID, nullptr, ng, p_pool, 0, NNODES);

    // ---- pooling counts + readout ----
    k_cnt<<<cdiv(NNODES, T), T>>>(ng, p_cnt, 0, NNODES);
    k_cnt<<<cdiv(NEDGES, T), T>>>(eg, p_cnt, NB, NEDGES);
    k_readout<<<NB, 128>>>(p_pool, p_cnt, r1w, r1b, r2w, r2b, out);
}